// round 4
// baseline (speedup 1.0000x reference)
#include <cuda_runtime.h>
#include <math.h>

#define OUTF 8192
#define INF_ 8192
#define NKCHUNKS 64
#define KCHUNK (INF_ / NKCHUNKS)          // 128
#define T1 256
#define COLS_PER_THREAD 4
#define COLBLOCKS 8                       // 8 * 64 = 512 blocks
#define NBLK (COLBLOCKS * NKCHUNKS)       // 512

// Scratch (no allocations allowed). Zero-initialized at module load; every
// launch leaves all of these back in the "zero" state (except g_att, which is
// fully overwritten each launch, and g_bar which cycles).
__device__ float g_hW[4 * OUTF];
__device__ float g_dist[6];
__device__ float g_att[9];
__device__ unsigned int g_bar[3];

// Grid-wide barrier. Safe because all NBLK blocks are guaranteed co-resident
// (launch_bounds(256,4) -> 592 slots >= 512). The last arriver at barrier
// `idx` resets the stale counter `reset_idx` (quiescent: nobody can arrive at
// barrier reset_idx again until after passing barrier idx+1, which requires
// this block's later arrival there).
__device__ __forceinline__ void grid_barrier(int idx, int reset_idx) {
    __syncthreads();
    if (threadIdx.x == 0) {
        __threadfence();                          // publish this block's writes
        unsigned int old = atomicAdd(&g_bar[idx], 1u);
        if (old == NBLK - 1u) {
            g_bar[reset_idx] = 0u;
            __threadfence();
        }
        while (atomicAdd(&g_bar[idx], 0u) < (unsigned)NBLK) {
            __nanosleep(64);
        }
    }
    __syncthreads();
    __threadfence();                              // acquire
}

// ---------------------------------------------------------------------------
// Persistent kernel: GEMM -> distances -> attention -> h_prime, one launch.
// ---------------------------------------------------------------------------
__global__ void __launch_bounds__(T1, 4) gat_kernel(const float* __restrict__ h,
                                                    const int* __restrict__ adj,
                                                    const float* __restrict__ W,
                                                    float* __restrict__ out,
                                                    int out_size) {
    __shared__ float hs[4][KCHUNK];
    __shared__ float red[6][8];
    const int tid = threadIdx.x;
    const int b   = blockIdx.x;

    // ===== Phase 1: split-K GEMM, atomic accumulate into g_hW (starts zero) ==
    {
        const int colblock = b & (COLBLOCKS - 1);
        const int kchunk   = b >> 3;
        const int k0 = kchunk * KCHUNK;

        for (int i = tid; i < 4 * KCHUNK; i += T1) {
            int m  = i / KCHUNK;
            int kk = i % KCHUNK;
            hs[m][kk] = h[m * INF_ + k0 + kk];
        }
        __syncthreads();

        const int col = (colblock * T1 + tid) * COLS_PER_THREAD;
        const float4* __restrict__ Wp = (const float4*)(W + (size_t)k0 * OUTF + col);
        const int rowstride4 = OUTF / 4;

        float4 a0 = make_float4(0.f, 0.f, 0.f, 0.f);
        float4 a1 = make_float4(0.f, 0.f, 0.f, 0.f);
        float4 a2 = make_float4(0.f, 0.f, 0.f, 0.f);
        float4 a3 = make_float4(0.f, 0.f, 0.f, 0.f);

#pragma unroll 8
        for (int kk = 0; kk < KCHUNK; kk++) {
            float4 w = Wp[(size_t)kk * rowstride4];
            float h0 = hs[0][kk], h1 = hs[1][kk], h2 = hs[2][kk], h3 = hs[3][kk];
            a0.x += h0 * w.x; a0.y += h0 * w.y; a0.z += h0 * w.z; a0.w += h0 * w.w;
            a1.x += h1 * w.x; a1.y += h1 * w.y; a1.z += h1 * w.z; a1.w += h1 * w.w;
            a2.x += h2 * w.x; a2.y += h2 * w.y; a2.z += h2 * w.z; a2.w += h2 * w.w;
            a3.x += h3 * w.x; a3.y += h3 * w.y; a3.z += h3 * w.z; a3.w += h3 * w.w;
        }

        atomicAdd(&g_hW[0 * OUTF + col + 0], a0.x);
        atomicAdd(&g_hW[0 * OUTF + col + 1], a0.y);
        atomicAdd(&g_hW[0 * OUTF + col + 2], a0.z);
        atomicAdd(&g_hW[0 * OUTF + col + 3], a0.w);
        atomicAdd(&g_hW[1 * OUTF + col + 0], a1.x);
        atomicAdd(&g_hW[1 * OUTF + col + 1], a1.y);
        atomicAdd(&g_hW[1 * OUTF + col + 2], a1.z);
        atomicAdd(&g_hW[1 * OUTF + col + 3], a1.w);
        atomicAdd(&g_hW[2 * OUTF + col + 0], a2.x);
        atomicAdd(&g_hW[2 * OUTF + col + 1], a2.y);
        atomicAdd(&g_hW[2 * OUTF + col + 2], a2.z);
        atomicAdd(&g_hW[2 * OUTF + col + 3], a2.w);
        atomicAdd(&g_hW[3 * OUTF + col + 0], a3.x);
        atomicAdd(&g_hW[3 * OUTF + col + 1], a3.y);
        atomicAdd(&g_hW[3 * OUTF + col + 2], a3.z);
        atomicAdd(&g_hW[3 * OUTF + col + 3], a3.w);
    }

    grid_barrier(0, 2);

    // ===== Phase 2: squared distances (blocks 0..31, one col per thread) ====
    if (b < 32) {
        const int k = b * T1 + tid;     // 0..8191
        float x0 = g_hW[0 * OUTF + k];
        float x1 = g_hW[1 * OUTF + k];
        float x2 = g_hW[2 * OUTF + k];
        float x3 = g_hW[3 * OUTF + k];
        float d;
        float s01, s02, s03, s12, s13, s23;
        d = x0 - x1; s01 = d * d;
        d = x0 - x2; s02 = d * d;
        d = x0 - x3; s03 = d * d;
        d = x1 - x2; s12 = d * d;
        d = x1 - x3; s13 = d * d;
        d = x2 - x3; s23 = d * d;
#pragma unroll
        for (int off = 16; off > 0; off >>= 1) {
            s01 += __shfl_down_sync(0xffffffffu, s01, off);
            s02 += __shfl_down_sync(0xffffffffu, s02, off);
            s03 += __shfl_down_sync(0xffffffffu, s03, off);
            s12 += __shfl_down_sync(0xffffffffu, s12, off);
            s13 += __shfl_down_sync(0xffffffffu, s13, off);
            s23 += __shfl_down_sync(0xffffffffu, s23, off);
        }
        int w = tid >> 5, l = tid & 31;
        if (l == 0) {
            red[0][w] = s01; red[1][w] = s02; red[2][w] = s03;
            red[3][w] = s12; red[4][w] = s13; red[5][w] = s23;
        }
        __syncthreads();
        if (tid == 0) {
            float t0 = 0.f, t1 = 0.f, t2 = 0.f, t3 = 0.f, t4 = 0.f, t5 = 0.f;
            for (int i = 0; i < 8; i++) {
                t0 += red[0][i]; t1 += red[1][i]; t2 += red[2][i];
                t3 += red[3][i]; t4 += red[4][i]; t5 += red[5][i];
            }
            atomicAdd(&g_dist[0], t0);
            atomicAdd(&g_dist[1], t1);
            atomicAdd(&g_dist[2], t2);
            atomicAdd(&g_dist[3], t3);
            atomicAdd(&g_dist[4], t4);
            atomicAdd(&g_dist[5], t5);
        }
    }

    grid_barrier(1, 0);

    // ===== Phase 3: attention (block 0, thread 0) ===========================
    if (b == 0 && tid == 0) {
        float t0 = g_dist[0], t1 = g_dist[1], t2 = g_dist[2];
        float t3 = g_dist[3], t4 = g_dist[4], t5 = g_dist[5];
        // reset for next launch (only this thread ever reads g_dist)
        g_dist[0] = 0.f; g_dist[1] = 0.f; g_dist[2] = 0.f;
        g_dist[3] = 0.f; g_dist[4] = 0.f; g_dist[5] = 0.f;

        // zero-safe sqrt (matches reference _cdist)
        float d01 = (t0 > 0.f) ? sqrtf(t0) : 0.f;
        float d02 = (t1 > 0.f) ? sqrtf(t1) : 0.f;
        float d03 = (t2 > 0.f) ? sqrtf(t2) : 0.f;
        float d12 = (t3 > 0.f) ? sqrtf(t3) : 0.f;
        float d13 = (t4 > 0.f) ? sqrtf(t4) : 0.f;
        float d23 = (t5 > 0.f) ? sqrtf(t5) : 0.f;
        // leaky_relu is identity for x >= 0 (distances nonnegative)
        float v01 = d12 + 0.5f * (d01 + d02);
        float v02 = d13 + 0.5f * (d01 + d03);
        float v12 = d23 + 0.5f * (d02 + d03);

        float e[3][3] = {{0.f, v01, v02},
                         {v01, 0.f, v12},
                         {v02, v12, 0.f}};

        for (int j = 0; j < 3; j++) {
            float c[3];
            for (int i = 0; i < 3; i++)
                c[i] = (adj[i * 3 + j] > 0) ? e[i][j] : -9e15f;
            float mx = fmaxf(c[0], fmaxf(c[1], c[2]));
            float ex0 = expf(c[0] - mx);
            float ex1 = expf(c[1] - mx);
            float ex2 = expf(c[2] - mx);
            float inv = 1.0f / (ex0 + ex1 + ex2);
            g_att[0 * 3 + j] = ex0 * inv;
            g_att[1 * 3 + j] = ex1 * inv;
            g_att[2 * 3 + j] = ex2 * inv;
        }
        out[out_size - 3] = v01;
        out[out_size - 2] = v02;
        out[out_size - 1] = v12;
    }

    grid_barrier(2, 1);

    // ===== Phase 4: h_prime + output assembly + zero own g_hW slice =========
    // 2048 float4 columns over 512 blocks -> 4 per block (threads 0..3).
    if (tid < 4) {
        const float a00 = g_att[0], a01 = g_att[1], a02 = g_att[2];
        const float a10 = g_att[3], a11 = g_att[4], a12 = g_att[5];
        const float a20 = g_att[6], a21 = g_att[7], a22 = g_att[8];
        const float4* hw = (const float4*)g_hW;
        float4* hwm = (float4*)g_hW;
        float4* o = (float4*)out;
        const int N4 = OUTF / 4;
        const int c = b * 4 + tid;

        float4 r0 = hw[0 * N4 + c];
        float4 b0 = hw[1 * N4 + c];
        float4 b1 = hw[2 * N4 + c];
        float4 b2 = hw[3 * N4 + c];

        o[c] = r0;
        float4 r;
        r.x = a00 * b0.x + a01 * b1.x + a02 * b2.x;
        r.y = a00 * b0.y + a01 * b1.y + a02 * b2.y;
        r.z = a00 * b0.z + a01 * b1.z + a02 * b2.z;
        r.w = a00 * b0.w + a01 * b1.w + a02 * b2.w;
        o[1 * N4 + c] = r;
        r.x = a10 * b0.x + a11 * b1.x + a12 * b2.x;
        r.y = a10 * b0.y + a11 * b1.y + a12 * b2.y;
        r.z = a10 * b0.z + a11 * b1.z + a12 * b2.z;
        r.w = a10 * b0.w + a11 * b1.w + a12 * b2.w;
        o[2 * N4 + c] = r;
        r.x = a20 * b0.x + a21 * b1.x + a22 * b2.x;
        r.y = a20 * b0.y + a21 * b1.y + a22 * b2.y;
        r.z = a20 * b0.z + a21 * b1.z + a22 * b2.z;
        r.w = a20 * b0.w + a21 * b1.w + a22 * b2.w;
        o[3 * N4 + c] = r;

        // leave scratch zeroed for the next launch (this block owns col c)
        float4 z = make_float4(0.f, 0.f, 0.f, 0.f);
        hwm[0 * N4 + c] = z;
        hwm[1 * N4 + c] = z;
        hwm[2 * N4 + c] = z;
        hwm[3 * N4 + c] = z;
    }
}

// ---------------------------------------------------------------------------
extern "C" void kernel_launch(void* const* d_in, const int* in_sizes, int n_in,
                              void* d_out, int out_size) {
    const float* h   = (const float*)d_in[0];   // [4, 8192]
    const int*   adj = (const int*)d_in[1];     // [3, 3]
    const float* W   = (const float*)d_in[2];   // [8192, 8192]
    float* out = (float*)d_out;

    gat_kernel<<<NBLK, T1>>>(h, adj, W, out, out_size);
}

// round 10
// speedup vs baseline: 1.1463x; 1.1463x over previous
#include <cuda_runtime.h>
#include <math.h>

#define OUTF 8192
#define INF_ 8192
#define NKCHUNKS 64
#define KCHUNK (INF_ / NKCHUNKS)          // 128
#define T1 256
#define COLS_PER_THREAD 4
#define COLBLOCKS 8                       // 8 * 64 = 512 blocks
#define NBLK (COLBLOCKS * NKCHUNKS)       // 512

// Scratch (no allocations allowed). Zero-initialized at module load; the
// finisher block restores everything to zero at the end of every launch, so
// graph replays are deterministic.
__device__ float g_hW[4 * OUTF];
__device__ unsigned int g_counter;

__device__ __forceinline__ void red_add_v4(float* ptr, float4 v) {
    asm volatile("red.global.add.v4.f32 [%0], {%1, %2, %3, %4};"
                 :: "l"(ptr), "f"(v.x), "f"(v.y), "f"(v.z), "f"(v.w)
                 : "memory");
}

// ---------------------------------------------------------------------------
// Single kernel: split-K GEMM (all blocks) -> last arriving block finishes
// distances -> softmax -> h_prime -> output, then resets scratch.
// ---------------------------------------------------------------------------
__global__ void __launch_bounds__(T1, 4) gat_kernel(const float* __restrict__ h,
                                                    const int* __restrict__ adj,
                                                    const float* __restrict__ W,
                                                    float* __restrict__ out,
                                                    int out_size) {
    __shared__ float hs[4][KCHUNK];
    __shared__ float red_s[6][8];
    __shared__ float att_s[9];
    __shared__ int s_last;
    const int tid = threadIdx.x;
    const int b   = blockIdx.x;

    // ===== Phase 1: split-K GEMM, vectorized RED accumulate into g_hW =======
    {
        const int colblock = b & (COLBLOCKS - 1);
        const int kchunk   = b >> 3;
        const int k0 = kchunk * KCHUNK;

        for (int i = tid; i < 4 * KCHUNK; i += T1) {
            int m  = i / KCHUNK;
            int kk = i % KCHUNK;
            hs[m][kk] = h[m * INF_ + k0 + kk];
        }
        __syncthreads();

        const int col = (colblock * T1 + tid) * COLS_PER_THREAD;
        const float4* __restrict__ Wp = (const float4*)(W + (size_t)k0 * OUTF + col);
        const int rowstride4 = OUTF / 4;

        float4 a0 = make_float4(0.f, 0.f, 0.f, 0.f);
        float4 a1 = make_float4(0.f, 0.f, 0.f, 0.f);
        float4 a2 = make_float4(0.f, 0.f, 0.f, 0.f);
        float4 a3 = make_float4(0.f, 0.f, 0.f, 0.f);

#pragma unroll 8
        for (int kk = 0; kk < KCHUNK; kk++) {
            float4 w = Wp[(size_t)kk * rowstride4];
            float h0 = hs[0][kk], h1 = hs[1][kk], h2 = hs[2][kk], h3 = hs[3][kk];
            a0.x += h0 * w.x; a0.y += h0 * w.y; a0.z += h0 * w.z; a0.w += h0 * w.w;
            a1.x += h1 * w.x; a1.y += h1 * w.y; a1.z += h1 * w.z; a1.w += h1 * w.w;
            a2.x += h2 * w.x; a2.y += h2 * w.y; a2.z += h2 * w.z; a2.w += h2 * w.w;
            a3.x += h3 * w.x; a3.y += h3 * w.y; a3.z += h3 * w.z; a3.w += h3 * w.w;
        }

        red_add_v4(&g_hW[0 * OUTF + col], a0);
        red_add_v4(&g_hW[1 * OUTF + col], a1);
        red_add_v4(&g_hW[2 * OUTF + col], a2);
        red_add_v4(&g_hW[3 * OUTF + col], a3);
    }

    // ===== Arrival counter: only the 512th arriver continues ================
    __threadfence();                    // publish this block's RED ops
    __syncthreads();
    if (tid == 0) {
        unsigned int old = atomicAdd(&g_counter, 1u);
        s_last = (old == NBLK - 1u) ? 1 : 0;
    }
    __syncthreads();
    if (!s_last) return;
    __threadfence();                    // acquire: all blocks' REDs visible

    // ===== Phase 2: squared distances (256 threads, 8 iters each) ===========
    {
        float s01 = 0.f, s02 = 0.f, s03 = 0.f, s12 = 0.f, s13 = 0.f, s23 = 0.f;
        const float4* hw = (const float4*)g_hW;
        const int N4 = OUTF / 4;
#pragma unroll
        for (int it = 0; it < N4 / T1; it++) {
            int c = it * T1 + tid;
            float4 x0 = hw[0 * N4 + c];
            float4 x1 = hw[1 * N4 + c];
            float4 x2 = hw[2 * N4 + c];
            float4 x3 = hw[3 * N4 + c];
            float d;
            d = x0.x - x1.x; s01 += d * d; d = x0.y - x1.y; s01 += d * d;
            d = x0.z - x1.z; s01 += d * d; d = x0.w - x1.w; s01 += d * d;
            d = x0.x - x2.x; s02 += d * d; d = x0.y - x2.y; s02 += d * d;
            d = x0.z - x2.z; s02 += d * d; d = x0.w - x2.w; s02 += d * d;
            d = x0.x - x3.x; s03 += d * d; d = x0.y - x3.y; s03 += d * d;
            d = x0.z - x3.z; s03 += d * d; d = x0.w - x3.w; s03 += d * d;
            d = x1.x - x2.x; s12 += d * d; d = x1.y - x2.y; s12 += d * d;
            d = x1.z - x2.z; s12 += d * d; d = x1.w - x2.w; s12 += d * d;
            d = x1.x - x3.x; s13 += d * d; d = x1.y - x3.y; s13 += d * d;
            d = x1.z - x3.z; s13 += d * d; d = x1.w - x3.w; s13 += d * d;
            d = x2.x - x3.x; s23 += d * d; d = x2.y - x3.y; s23 += d * d;
            d = x2.z - x3.z; s23 += d * d; d = x2.w - x3.w; s23 += d * d;
        }
#pragma unroll
        for (int off = 16; off > 0; off >>= 1) {
            s01 += __shfl_down_sync(0xffffffffu, s01, off);
            s02 += __shfl_down_sync(0xffffffffu, s02, off);
            s03 += __shfl_down_sync(0xffffffffu, s03, off);
            s12 += __shfl_down_sync(0xffffffffu, s12, off);
            s13 += __shfl_down_sync(0xffffffffu, s13, off);
            s23 += __shfl_down_sync(0xffffffffu, s23, off);
        }
        int w = tid >> 5, l = tid & 31;
        if (l == 0) {
            red_s[0][w] = s01; red_s[1][w] = s02; red_s[2][w] = s03;
            red_s[3][w] = s12; red_s[4][w] = s13; red_s[5][w] = s23;
        }
    }
    __syncthreads();

    // ===== Phase 3: attention softmax (thread 0) ============================
    if (tid == 0) {
        float t[6];
        for (int j = 0; j < 6; j++) {
            float s = 0.f;
            for (int i = 0; i < 8; i++) s += red_s[j][i];
            t[j] = s;
        }
        // zero-safe sqrt (matches reference _cdist)
        float d01 = (t[0] > 0.f) ? sqrtf(t[0]) : 0.f;
        float d02 = (t[1] > 0.f) ? sqrtf(t[1]) : 0.f;
        float d03 = (t[2] > 0.f) ? sqrtf(t[2]) : 0.f;
        float d12 = (t[3] > 0.f) ? sqrtf(t[3]) : 0.f;
        float d13 = (t[4] > 0.f) ? sqrtf(t[4]) : 0.f;
        float d23 = (t[5] > 0.f) ? sqrtf(t[5]) : 0.f;
        // leaky_relu is identity for x >= 0 (distances nonnegative)
        float v01 = d12 + 0.5f * (d01 + d02);
        float v02 = d13 + 0.5f * (d01 + d03);
        float v12 = d23 + 0.5f * (d02 + d03);

        float e[3][3] = {{0.f, v01, v02},
                         {v01, 0.f, v12},
                         {v02, v12, 0.f}};

        for (int j = 0; j < 3; j++) {
            float c[3];
            for (int i = 0; i < 3; i++)
                c[i] = (adj[i * 3 + j] > 0) ? e[i][j] : -9e15f;
            float mx = fmaxf(c[0], fmaxf(c[1], c[2]));
            float ex0 = expf(c[0] - mx);
            float ex1 = expf(c[1] - mx);
            float ex2 = expf(c[2] - mx);
            float inv = 1.0f / (ex0 + ex1 + ex2);
            att_s[0 * 3 + j] = ex0 * inv;
            att_s[1 * 3 + j] = ex1 * inv;
            att_s[2 * 3 + j] = ex2 * inv;
        }
        out[out_size - 3] = v01;
        out[out_size - 2] = v02;
        out[out_size - 1] = v12;
    }
    __syncthreads();

    // ===== Phase 4: h_prime + output + zero scratch =========================
    {
        const float a00 = att_s[0], a01 = att_s[1], a02 = att_s[2];
        const float a10 = att_s[3], a11 = att_s[4], a12 = att_s[5];
        const float a20 = att_s[6], a21 = att_s[7], a22 = att_s[8];
        const float4* hw = (const float4*)g_hW;
        float4* hwm = (float4*)g_hW;
        float4* o = (float4*)out;
        const int N4 = OUTF / 4;
        const float4 z = make_float4(0.f, 0.f, 0.f, 0.f);

#pragma unroll
        for (int it = 0; it < N4 / T1; it++) {
            int c = it * T1 + tid;
            float4 r0 = hw[0 * N4 + c];      // L1 hits (read in phase 2)
            float4 b0 = hw[1 * N4 + c];
            float4 b1 = hw[2 * N4 + c];
            float4 b2 = hw[3 * N4 + c];

            o[c] = r0;
            float4 r;
            r.x = a00 * b0.x + a01 * b1.x + a02 * b2.x;
            r.y = a00 * b0.y + a01 * b1.y + a02 * b2.y;
            r.z = a00 * b0.z + a01 * b1.z + a02 * b2.z;
            r.w = a00 * b0.w + a01 * b1.w + a02 * b2.w;
            o[1 * N4 + c] = r;
            r.x = a10 * b0.x + a11 * b1.x + a12 * b2.x;
            r.y = a10 * b0.y + a11 * b1.y + a12 * b2.y;
            r.z = a10 * b0.z + a11 * b1.z + a12 * b2.z;
            r.w = a10 * b0.w + a11 * b1.w + a12 * b2.w;
            o[2 * N4 + c] = r;
            r.x = a20 * b0.x + a21 * b1.x + a22 * b2.x;
            r.y = a20 * b0.y + a21 * b1.y + a22 * b2.y;
            r.z = a20 * b0.z + a21 * b1.z + a22 * b2.z;
            r.w = a20 * b0.w + a21 * b1.w + a22 * b2.w;
            o[3 * N4 + c] = r;

            // restore scratch to zero for the next (graph-replayed) launch
            hwm[0 * N4 + c] = z;
            hwm[1 * N4 + c] = z;
            hwm[2 * N4 + c] = z;
            hwm[3 * N4 + c] = z;
        }
    }
    __syncthreads();
    if (tid == 0) g_counter = 0u;           // only this block is still alive
}

// ---------------------------------------------------------------------------
extern "C" void kernel_launch(void* const* d_in, const int* in_sizes, int n_in,
                              void* d_out, int out_size) {
    const float* h   = (const float*)d_in[0];   // [4, 8192]
    const int*   adj = (const int*)d_in[1];     // [3, 3]
    const float* W   = (const float*)d_in[2];   // [8192, 8192]
    float* out = (float*)d_out;

    gat_kernel<<<NBLK, T1>>>(h, adj, W, out, out_size);
}